// round 16
// baseline (speedup 1.0000x reference)
#include <cuda_runtime.h>
#include <cuda_fp16.h>
#include <cstdint>

#define TOKENS 262144      // 4 * 256 * 256
#define CDIM   192
#define QKVN   576
#define NHEADS 6
#define NWINS  4096

__device__ __half g_xh[(size_t)TOKENS * CDIM];    // fp16 x
__device__ __half g_qkv[(size_t)TOKENS * QKVN];   // fp16 qkv
__device__ __half g_att[(size_t)TOKENS * CDIM];   // fp16 attention out
__device__ __half g_wq[(size_t)QKVN * CDIM];      // fp16 qkv_w
__device__ __half g_wp[(size_t)CDIM * CDIM];      // fp16 proj_w

__device__ __forceinline__ uint32_t smem_u32(const void* p) {
    uint32_t a;
    asm("{ .reg .u64 t; cvta.to.shared.u64 t, %1; cvt.u32.u64 %0, t; }" : "=r"(a) : "l"(p));
    return a;
}
__device__ __forceinline__ uint32_t pack_h2(float lo, float hi) {
    __half2 h = __floats2half2_rn(lo, hi);
    return *(uint32_t*)&h;
}
__device__ __forceinline__ void mma_f16(float* c, const uint32_t* a, const uint32_t* b) {
    asm volatile(
        "mma.sync.aligned.m16n8k16.row.col.f32.f16.f16.f32 "
        "{%0,%1,%2,%3}, {%4,%5,%6,%7}, {%8,%9}, {%0,%1,%2,%3};"
        : "+f"(c[0]), "+f"(c[1]), "+f"(c[2]), "+f"(c[3])
        : "r"(a[0]), "r"(a[1]), "r"(a[2]), "r"(a[3]), "r"(b[0]), "r"(b[1]));
}
__device__ __forceinline__ void cpa16(uint32_t dst, const void* src) {
    asm volatile("cp.async.cg.shared.global [%0], [%1], 16;" :: "r"(dst), "l"(src));
}
__device__ __forceinline__ void cpa_commit() {
    asm volatile("cp.async.commit_group;" ::: "memory");
}
template<int N>
__device__ __forceinline__ void cpa_wait() {
    asm volatile("cp.async.wait_group %0;" :: "n"(N) : "memory");
}

// convert weights to fp16 once
__global__ void round_weights(const float* __restrict__ qw, const float* __restrict__ pw)
{
    int i = blockIdx.x * 256 + threadIdx.x;
    if (i < QKVN * CDIM) g_wq[i] = __float2half_rn(qw[i]);
    if (i < CDIM * CDIM) g_wp[i] = __float2half_rn(pw[i]);
}

// convert x to fp16 once (8 elems/thread)
__global__ __launch_bounds__(256) void cvt_x(const float* __restrict__ x)
{
    size_t i = ((size_t)blockIdx.x * 256 + threadIdx.x) * 8;
    float4 a = *(const float4*)(x + i);
    float4 b = *(const float4*)(x + i + 4);
    uint4 o;
    o.x = pack_h2(a.x, a.y); o.y = pack_h2(a.z, a.w);
    o.z = pack_h2(b.x, b.y); o.w = pack_h2(b.z, b.w);
    *(uint4*)(g_xh + i) = o;
}

// epilogue store helpers
__device__ __forceinline__ void store_pair(__half* C, size_t idx, float v0, float v1) {
    ((uint32_t*)C)[idx >> 1] = pack_h2(v0, v1);     // idx even
}
__device__ __forceinline__ void store_pair(float* C, size_t idx, float v0, float v1) {
    *(float2*)(C + idx) = make_float2(v0, v1);
}

// ---------------- fp16 warp-mma GEMM, 2-stage cp.async (both operands fp16) ----------------
// C[m][n] = sum_k A[m][k]*W[n][k] + bias[n]
// Block 128x96, 8 warps (4m x 2n), warp tile 32x48, BK=32, K=192 (6 slabs).
// fp16 smem rows: 32 halfs = 16 u32, padded to 20 u32 (80B) -> conflict-free frags.
template<int NOUT, typename OT>
__global__ __launch_bounds__(256) void gemm_mma(
    const __half* __restrict__ A, const __half* __restrict__ W,
    const float* __restrict__ bias, OT* __restrict__ C)
{
    extern __shared__ __align__(16) char smc[];
    char* Abase = smc;                              // 2 * 10240
    char* Bbase = smc + 20480;                      // 2 * 7680
    const uint32_t AS = smem_u32(Abase);
    const uint32_t BS = smem_u32(Bbase);

    const int t    = threadIdx.x;
    const int wid  = t >> 5;
    const int lane = t & 31;
    const int bm   = blockIdx.y * 128;
    const int bn   = blockIdx.x * 96;
    const int m0   = (wid >> 1) * 32;
    const int n0   = (wid & 1) * 48;
    const int gr   = lane >> 2;
    const int gc   = lane & 3;

    float acc[2][6][4];
#pragma unroll
    for (int i = 0; i < 2; ++i)
#pragma unroll
        for (int j = 0; j < 6; ++j)
#pragma unroll
            for (int r = 0; r < 4; ++r) acc[i][j][r] = 0.f;

    auto stage = [&](int slab, int buf) {
        const int k0 = slab * 32;
#pragma unroll
        for (int p = 0; p < 2; ++p) {               // 512 chunks of 16B
            int ci = t + p * 256;
            int r = ci >> 2, c = ci & 3;
            cpa16(AS + buf * 10240 + r * 80 + c * 16,
                  (const char*)A + ((size_t)(bm + r) * CDIM + k0 + c * 8) * 2);
        }
#pragma unroll
        for (int p = 0; p < 2; ++p) {               // 384 chunks of 16B
            int ci = t + p * 256;
            if (ci < 384) {
                int r = ci >> 2, c = ci & 3;
                cpa16(BS + buf * 7680 + r * 80 + c * 16,
                      (const char*)W + ((size_t)(bn + r) * CDIM + k0 + c * 8) * 2);
            }
        }
        cpa_commit();
    };

    stage(0, 0);

#pragma unroll
    for (int s = 0; s < 6; ++s) {
        const int buf = s & 1;
        if (s + 1 < 6) stage(s + 1, buf ^ 1);
        if (s + 1 < 6) cpa_wait<1>(); else cpa_wait<0>();
        __syncthreads();

        const uint32_t* Ash = (const uint32_t*)(Abase + buf * 10240);  // stride 20 u32
        const uint32_t* Bs  = (const uint32_t*)(Bbase + buf * 7680);   // stride 20 u32

#pragma unroll
        for (int ks = 0; ks < 2; ++ks) {            // 2 x k16 per BK=32
            const int kk2 = ks * 8;
            uint32_t af[2][4], bf[6][2];
#pragma unroll
            for (int mi = 0; mi < 2; ++mi) {
                int rb = m0 + mi * 16 + gr;
                af[mi][0] = Ash[rb * 20 + kk2 + gc];
                af[mi][1] = Ash[(rb + 8) * 20 + kk2 + gc];
                af[mi][2] = Ash[rb * 20 + kk2 + gc + 4];
                af[mi][3] = Ash[(rb + 8) * 20 + kk2 + gc + 4];
            }
#pragma unroll
            for (int ni = 0; ni < 6; ++ni) {
                int nb = n0 + ni * 8 + gr;
                bf[ni][0] = Bs[nb * 20 + kk2 + gc];
                bf[ni][1] = Bs[nb * 20 + kk2 + gc + 4];
            }
#pragma unroll
            for (int mi = 0; mi < 2; ++mi)
#pragma unroll
                for (int ni = 0; ni < 6; ++ni)
                    mma_f16(acc[mi][ni], af[mi], bf[ni]);
        }
        __syncthreads();
    }

#pragma unroll
    for (int mi = 0; mi < 2; ++mi) {
        int mr = bm + m0 + mi * 16 + gr;
#pragma unroll
        for (int ni = 0; ni < 6; ++ni) {
            int nc = bn + n0 + ni * 8 + gc * 2;
            float2 bv = __ldg((const float2*)(bias + nc));
            store_pair(C, (size_t)mr * NOUT + nc,       acc[mi][ni][0] + bv.x, acc[mi][ni][1] + bv.y);
            store_pair(C, (size_t)(mr + 8) * NOUT + nc, acc[mi][ni][2] + bv.x, acc[mi][ni][3] + bv.y);
        }
    }
}

// ---------------- fp16 window attention, 2 heads per block ----------------
// One block (256 thr, 8 warps) per (window, head-pair). Heads are adjacent in the
// token record -> gather reads 128B contiguous per (token, stream). q/k via cp.async.
// Warp w: hsel = w>>2 (which head), rows [16*(w&3), +16).
__global__ __launch_bounds__(256) void win_attn(const float* __restrict__ bias)
{
    __shared__ __align__(16) uint32_t qs_[2][64 * 20];
    __shared__ __align__(16) uint32_t ks_[2][64 * 20];
    __shared__ __align__(16) uint32_t vsT[2][32 * 36];
    __shared__ __align__(16) uint32_t ps_[2][64 * 36];

    const int hp   = blockIdx.x % 3;
    const int win  = blockIdx.x / 3;
    const int head0 = hp * 2;
    const int b  = win >> 10;
    const int wy = (win >> 5) & 31;
    const int wx = win & 31;

    const int t    = threadIdx.x;
    const int wid  = t >> 5;
    const int lane = t & 31;
    const int hsel = wid >> 2;
    const int wwid = wid & 3;
    const int gr   = lane >> 2;
    const int gc   = lane & 3;
    const float scale = 0.17677669529663687f;

    const uint32_t qsS = smem_u32(qs_);
    const uint32_t ksS = smem_u32(ks_);

    // gather: 64 tok x 8 chunks (2 heads x 4); q/k via cp.async, v via registers
#pragma unroll
    for (int i = 0; i < 2; ++i) {
        int idx = t + i * 256;
        int p = idx >> 3;
        int c = idx & 7;
        int ho = c >> 2;            // which head of the pair
        int cc = c & 3;
        int h = wy * 8 + (p >> 3);
        int w = wx * 8 + (p & 7);
        int tok = b * 65536 + h * 256 + w;
        const char* gb = (const char*)g_qkv + ((size_t)tok * QKVN + (head0 + ho) * 32) * 2;
        uint32_t so = (uint32_t)(ho * 5120 + p * 80 + cc * 16);
        cpa16(qsS + so, gb + cc * 16);
        cpa16(ksS + so, gb + 384 + cc * 16);
        uint4 vv = *(const uint4*)(gb + 768 + cc * 16);
        const unsigned short* us = (const unsigned short*)&vv;
#pragma unroll
        for (int j = 0; j < 8; ++j) {
            int d = cc * 8 + j;
            ((unsigned short*)vsT[ho])[d * 72 + p] = us[j];
        }
    }
    cpa_commit();
    cpa_wait<0>();
    __syncthreads();

    const uint32_t* qs = qs_[hsel];
    const uint32_t* ks = ks_[hsel];
    const uint32_t* vt = vsT[hsel];
    uint32_t*       ps = ps_[hsel];
    const int head = head0 + hsel;

    // S = q @ k^T  (warp: 16 rows x 64 cols), K=32 -> 2 k16 steps, 8 n-tiles
    const int m0 = wwid * 16;
    float s[8][4];
#pragma unroll
    for (int ni = 0; ni < 8; ++ni)
#pragma unroll
        for (int r = 0; r < 4; ++r) s[ni][r] = 0.f;

#pragma unroll
    for (int ks4 = 0; ks4 < 2; ++ks4) {
        const int kk2 = ks4 * 8;
        uint32_t a[4];
        a[0] = qs[(m0 + gr) * 20 + kk2 + gc];
        a[1] = qs[(m0 + gr + 8) * 20 + kk2 + gc];
        a[2] = qs[(m0 + gr) * 20 + kk2 + gc + 4];
        a[3] = qs[(m0 + gr + 8) * 20 + kk2 + gc + 4];
#pragma unroll
        for (int ni = 0; ni < 8; ++ni) {
            uint32_t bfr[2];
            bfr[0] = ks[(ni * 8 + gr) * 20 + kk2 + gc];
            bfr[1] = ks[(ni * 8 + gr) * 20 + kk2 + gc + 4];
            mma_f16(s[ni], a, bfr);
        }
    }

    // logits = s*scale + bias; register softmax (rows r0, r1)
    const int r0 = m0 + gr;
    const int r1 = r0 + 8;
    const float* bp = bias + head * 4096;
    float mx0 = -1e30f, mx1 = -1e30f;
#pragma unroll
    for (int ni = 0; ni < 8; ++ni) {
        float2 b0 = __ldg((const float2*)(bp + r0 * 64 + ni * 8 + gc * 2));
        float2 b1 = __ldg((const float2*)(bp + r1 * 64 + ni * 8 + gc * 2));
        s[ni][0] = s[ni][0] * scale + b0.x; s[ni][1] = s[ni][1] * scale + b0.y;
        s[ni][2] = s[ni][2] * scale + b1.x; s[ni][3] = s[ni][3] * scale + b1.y;
        mx0 = fmaxf(mx0, fmaxf(s[ni][0], s[ni][1]));
        mx1 = fmaxf(mx1, fmaxf(s[ni][2], s[ni][3]));
    }
    mx0 = fmaxf(mx0, __shfl_xor_sync(0xffffffffu, mx0, 1));
    mx0 = fmaxf(mx0, __shfl_xor_sync(0xffffffffu, mx0, 2));
    mx1 = fmaxf(mx1, __shfl_xor_sync(0xffffffffu, mx1, 1));
    mx1 = fmaxf(mx1, __shfl_xor_sync(0xffffffffu, mx1, 2));

    float sum0 = 0.f, sum1 = 0.f;
#pragma unroll
    for (int ni = 0; ni < 8; ++ni) {
        s[ni][0] = __expf(s[ni][0] - mx0);
        s[ni][1] = __expf(s[ni][1] - mx0);
        s[ni][2] = __expf(s[ni][2] - mx1);
        s[ni][3] = __expf(s[ni][3] - mx1);
        sum0 += s[ni][0] + s[ni][1];
        sum1 += s[ni][2] + s[ni][3];
    }
    sum0 += __shfl_xor_sync(0xffffffffu, sum0, 1);
    sum0 += __shfl_xor_sync(0xffffffffu, sum0, 2);
    sum1 += __shfl_xor_sync(0xffffffffu, sum1, 1);
    sum1 += __shfl_xor_sync(0xffffffffu, sum1, 2);
    const float inv0 = 1.f / sum0;
    const float inv1 = 1.f / sum1;

#pragma unroll
    for (int ni = 0; ni < 8; ++ni) {
        ps[r0 * 36 + ni * 4 + gc] = pack_h2(s[ni][0] * inv0, s[ni][1] * inv0);
        ps[r1 * 36 + ni * 4 + gc] = pack_h2(s[ni][2] * inv1, s[ni][3] * inv1);
    }
    __syncwarp();

    // O = P @ V  (warp: 16 rows x 32 d), K=64 -> 4 k16 steps, 4 n-tiles
    float o[4][4];
#pragma unroll
    for (int ni = 0; ni < 4; ++ni)
#pragma unroll
        for (int r = 0; r < 4; ++r) o[ni][r] = 0.f;

#pragma unroll
    for (int ks4 = 0; ks4 < 4; ++ks4) {
        const int kk2 = ks4 * 8;
        uint32_t a[4];
        a[0] = ps[(m0 + gr) * 36 + kk2 + gc];
        a[1] = ps[(m0 + gr + 8) * 36 + kk2 + gc];
        a[2] = ps[(m0 + gr) * 36 + kk2 + gc + 4];
        a[3] = ps[(m0 + gr + 8) * 36 + kk2 + gc + 4];
#pragma unroll
        for (int ni = 0; ni < 4; ++ni) {
            uint32_t bfr[2];
            bfr[0] = vt[(ni * 8 + gr) * 36 + kk2 + gc];
            bfr[1] = vt[(ni * 8 + gr) * 36 + kk2 + gc + 4];
            mma_f16(o[ni], a, bfr);
        }
    }

    // scatter O as fp16 to g_att
    {
        int h0 = wy * 8 + (r0 >> 3), w0 = wx * 8 + (r0 & 7);
        int h1 = wy * 8 + (r1 >> 3), w1 = wx * 8 + (r1 & 7);
        size_t tok0 = (size_t)(b * 65536 + h0 * 256 + w0) * CDIM + head * 32;
        size_t tok1 = (size_t)(b * 65536 + h1 * 256 + w1) * CDIM + head * 32;
        uint32_t* ga = (uint32_t*)g_att;
#pragma unroll
        for (int ni = 0; ni < 4; ++ni) {
            int d = ni * 8 + gc * 2;
            ga[(tok0 + d) >> 1] = pack_h2(o[ni][0], o[ni][1]);
            ga[(tok1 + d) >> 1] = pack_h2(o[ni][2], o[ni][3]);
        }
    }
}

extern "C" void kernel_launch(void* const* d_in, const int* in_sizes, int n_in,
                              void* d_out, int out_size)
{
    const float* x      = (const float*)d_in[0];
    const float* qkv_w  = (const float*)d_in[1];
    const float* qkv_b  = (const float*)d_in[2];
    const float* proj_w = (const float*)d_in[3];
    const float* proj_b = (const float*)d_in[4];
    const float* bias   = (const float*)d_in[5];
    float* out = (float*)d_out;

    __half *xh_p = nullptr, *qkv_p = nullptr, *att_p = nullptr, *wq_p = nullptr, *wp_p = nullptr;
    cudaGetSymbolAddress((void**)&xh_p, g_xh);
    cudaGetSymbolAddress((void**)&qkv_p, g_qkv);
    cudaGetSymbolAddress((void**)&att_p, g_att);
    cudaGetSymbolAddress((void**)&wq_p, g_wq);
    cudaGetSymbolAddress((void**)&wp_p, g_wp);

    const int smem_g = 2 * 10240 + 2 * 7680;   // 35840
    cudaFuncSetAttribute((const void*)gemm_mma<QKVN, __half>,
                         cudaFuncAttributeMaxDynamicSharedMemorySize, smem_g);
    cudaFuncSetAttribute((const void*)gemm_mma<CDIM, float>,
                         cudaFuncAttributeMaxDynamicSharedMemorySize, smem_g);

    // 0) weights + x -> fp16
    round_weights<<<(QKVN * CDIM + 255) / 256, 256>>>(qkv_w, proj_w);
    cvt_x<<<TOKENS * CDIM / (256 * 8), 256>>>(x);

    // 1) QKV GEMM: fp16 x -> fp16 g_qkv
    dim3 g1(QKVN / 96, TOKENS / 128);
    gemm_mma<QKVN, __half><<<g1, 256, smem_g>>>(xh_p, wq_p, qkv_b, qkv_p);

    // 2) Windowed attention (2 heads/block)
    win_attn<<<NWINS * 3, 256>>>(bias);

    // 3) Proj GEMM: fp16 g_att -> fp32 out
    dim3 g3(CDIM / 96, TOKENS / 128);
    gemm_mma<CDIM, float><<<g3, 256, smem_g>>>(att_p, wp_p, proj_b, out);
}